// round 1
// baseline (speedup 1.0000x reference)
#include <cuda_runtime.h>
#include <cuda_bf16.h>
#include <math.h>

// Problem constants
#define B_     64
#define S_     2048
#define D_     768
#define L_     2
#define POOL_  30
#define LEN_   5
#define TOPK_  5
#define SS_    16           // S split count
#define SCHUNK_ (S_ / SS_)  // 128

// Output layout (flattened tuple, fp32):
// s_batched [2,64,25,768] = 2457600
// t_batched [2,64,25,768] = 2457600
// s_similarity [64,30]    = 1920
// t_similarity [64,30]    = 1920
// s_reduce_sim, t_reduce_sim (scalars)
#define NB_ELEMS   (L_ * B_ * (TOPK_*LEN_) * D_)   // 2457600
#define OFF_SB     0
#define OFF_TB     (NB_ELEMS)
#define OFF_SSIM   (2 * NB_ELEMS)                  // 4915200
#define OFF_TSIM   (OFF_SSIM + B_ * POOL_)         // 4917120
#define OFF_SRED   (OFF_TSIM + B_ * POOL_)         // 4919040
#define OFF_TRED   (OFF_SRED + 1)

// Device scratch (static: no allocation allowed)
__device__ float g_partial[SS_ * B_ * D_];   // 3 MB partial sums
__device__ float g_skey[POOL_ * D_];
__device__ float g_tkey[POOL_ * D_];
__device__ int   g_sidx[B_ * TOPK_];
__device__ int   g_tidx[B_ * TOPK_];
__device__ float g_stop[B_];
__device__ float g_ttop[B_];

// ---------------------------------------------------------------------------
// Kernel A: partial mean over S chunks.  grid (B, SS), block 192 (float4/d)
// ---------------------------------------------------------------------------
__global__ void __launch_bounds__(192) k_mean_partial(const float* __restrict__ x) {
    int b  = blockIdx.x;
    int ss = blockIdx.y;
    int d4 = threadIdx.x;                     // 0..191, each owns 4 d's
    const float4* xp = reinterpret_cast<const float4*>(x)
                     + ((size_t)(b * S_ + ss * SCHUNK_)) * (D_ / 4) + d4;
    float4 acc = make_float4(0.f, 0.f, 0.f, 0.f);
#pragma unroll 8
    for (int s = 0; s < SCHUNK_; ++s) {
        float4 v = xp[(size_t)s * (D_ / 4)];
        acc.x += v.x; acc.y += v.y; acc.z += v.z; acc.w += v.w;
    }
    reinterpret_cast<float4*>(g_partial)[(ss * B_ + b) * (D_ / 4) + d4] = acc;
}

// ---------------------------------------------------------------------------
// Block reduce helper (256 threads)
// ---------------------------------------------------------------------------
__device__ __forceinline__ float block_reduce_256(float v, float* red) {
    int lane = threadIdx.x & 31, w = threadIdx.x >> 5;
#pragma unroll
    for (int o = 16; o; o >>= 1) v += __shfl_down_sync(0xffffffffu, v, o);
    if (lane == 0) red[w] = v;
    __syncthreads();
    if (w == 0) {
        v = (lane < 8) ? red[lane] : 0.f;
#pragma unroll
        for (int o = 4; o; o >>= 1) v += __shfl_down_sync(0xffffffffu, v, o);
        if (lane == 0) red[0] = v;
    }
    __syncthreads();
    return red[0];
}

// ---------------------------------------------------------------------------
// Kernel B: L2-normalize both key pools.  grid 60, block 256
// ---------------------------------------------------------------------------
__global__ void __launch_bounds__(256) k_norm_keys(const float* __restrict__ sk,
                                                   const float* __restrict__ tk) {
    int key = blockIdx.x;  // 0..59
    const float* src = (key < POOL_) ? (sk + key * D_) : (tk + (key - POOL_) * D_);
    float*       dst = (key < POOL_) ? (g_skey + key * D_) : (g_tkey + (key - POOL_) * D_);
    __shared__ float red[8];
    float sq = 0.f;
    for (int d = threadIdx.x; d < D_; d += 256) { float v = src[d]; sq += v * v; }
    float total = block_reduce_256(sq, red);
    float inv = rsqrtf(fmaxf(total, 1e-12f));
    for (int d = threadIdx.x; d < D_; d += 256) dst[d] = src[d] * inv;
}

// ---------------------------------------------------------------------------
// Kernel C: finalize per-batch: mean -> norm -> 60 dots -> top-5.
// grid 64, block 256
// ---------------------------------------------------------------------------
__global__ void __launch_bounds__(256) k_finalize(float* __restrict__ out) {
    int b = blockIdx.x;
    __shared__ float xn[D_];
    __shared__ float sim[2 * POOL_];
    __shared__ float red[8];

    // mean over 16 partials, accumulate |x_mean|^2
    float sq = 0.f;
    for (int d = threadIdx.x; d < D_; d += 256) {
        float s = 0.f;
#pragma unroll
        for (int ss = 0; ss < SS_; ++ss) s += g_partial[(ss * B_ + b) * D_ + d];
        float xm = s * (1.f / (float)S_);
        xn[d] = xm;
        sq += xm * xm;
    }
    float total = block_reduce_256(sq, red);
    float inv = rsqrtf(fmaxf(total, 1e-12f));
    for (int d = threadIdx.x; d < D_; d += 256) xn[d] *= inv;
    __syncthreads();

    // 60 dots: warp per key, round-robin
    int lane = threadIdx.x & 31, w = threadIdx.x >> 5;   // 8 warps
    for (int key = w; key < 2 * POOL_; key += 8) {
        const float* kp = (key < POOL_) ? (g_skey + key * D_)
                                        : (g_tkey + (key - POOL_) * D_);
        float dot = 0.f;
#pragma unroll
        for (int i = 0; i < D_ / 32; ++i) {
            int d = lane + i * 32;
            dot += kp[d] * xn[d];
        }
#pragma unroll
        for (int o = 16; o; o >>= 1) dot += __shfl_down_sync(0xffffffffu, dot, o);
        if (lane == 0) {
            sim[key] = dot;
            if (key < POOL_) out[OFF_SSIM + b * POOL_ + key] = dot;
            else             out[OFF_TSIM + b * POOL_ + (key - POOL_)] = dot;
        }
    }
    __syncthreads();

    // top-5 selection (threads 0 and 1); strict '>' keeps lowest index on ties
    if (threadIdx.x < 2) {
        const float* sm = sim + threadIdx.x * POOL_;
        int*   gi = (threadIdx.x == 0) ? g_sidx : g_tidx;
        float* gt = (threadIdx.x == 0) ? g_stop : g_ttop;
        float loc[POOL_];
#pragma unroll
        for (int i = 0; i < POOL_; ++i) loc[i] = sm[i];
        float topsum = 0.f;
#pragma unroll
        for (int k = 0; k < TOPK_; ++k) {
            int   bj = 0;
            float bv = loc[0];
#pragma unroll
            for (int i = 1; i < POOL_; ++i) {
                if (loc[i] > bv) { bv = loc[i]; bj = i; }
            }
            gi[b * TOPK_ + k] = bj;
            topsum += bv;
            loc[bj] = -INFINITY;
        }
        gt[b] = topsum;
    }
}

// ---------------------------------------------------------------------------
// Kernel D: gather prompts. grid 6400, block 192 (one 768-float row each)
//   block decode: tensor(2) x l(2) x b(64) x kk(25)
// ---------------------------------------------------------------------------
__global__ void __launch_bounds__(192) k_gather(const float* __restrict__ sp,
                                                const float* __restrict__ tp,
                                                float* __restrict__ out) {
    int bi = blockIdx.x;
    int tensor = bi / (L_ * B_ * TOPK_ * LEN_);       // /3200
    int rem    = bi % (L_ * B_ * TOPK_ * LEN_);
    int l  = rem / (B_ * TOPK_ * LEN_);               // /1600
    int r2 = rem % (B_ * TOPK_ * LEN_);
    int b  = r2 / (TOPK_ * LEN_);                     // /25
    int kk = r2 % (TOPK_ * LEN_);
    int k  = kk / LEN_;
    int t  = kk % LEN_;

    int idx = tensor ? g_tidx[b * TOPK_ + k] : g_sidx[b * TOPK_ + k];
    const float* srcbase = tensor ? tp : sp;
    const float4* src = reinterpret_cast<const float4*>(
        srcbase + ((size_t)((l * POOL_ + idx) * LEN_ + t)) * D_);
    float4* dst = reinterpret_cast<float4*>(
        out + (tensor ? OFF_TB : OFF_SB)
            + ((size_t)((l * B_ + b) * (TOPK_ * LEN_) + kk)) * D_);
    dst[threadIdx.x] = src[threadIdx.x];
}

// ---------------------------------------------------------------------------
// Kernel E: reduce-sim scalars
// ---------------------------------------------------------------------------
__global__ void k_scalars(float* __restrict__ out) {
    if (threadIdx.x == 0) {
        float s = 0.f;
        for (int i = 0; i < B_; ++i) s += g_stop[i];
        out[OFF_SRED] = s / (float)B_;
    }
    if (threadIdx.x == 1) {
        float s = 0.f;
        for (int i = 0; i < B_; ++i) s += g_ttop[i];
        out[OFF_TRED] = s / (float)B_;
    }
}

// ---------------------------------------------------------------------------
extern "C" void kernel_launch(void* const* d_in, const int* in_sizes, int n_in,
                              void* d_out, int out_size) {
    (void)in_sizes; (void)n_in; (void)out_size;
    const float* x_embed = (const float*)d_in[0];
    const float* s_prompt = (const float*)d_in[1];
    const float* t_prompt = (const float*)d_in[2];
    const float* s_key = (const float*)d_in[3];
    const float* t_key = (const float*)d_in[4];
    float* out = (float*)d_out;

    k_mean_partial<<<dim3(B_, SS_), 192>>>(x_embed);
    k_norm_keys<<<2 * POOL_, 256>>>(s_key, t_key);
    k_finalize<<<B_, 256>>>(out);
    k_gather<<<2 * L_ * B_ * TOPK_ * LEN_, 192>>>(s_prompt, t_prompt, out);
    k_scalars<<<1, 32>>>(out);
}

// round 2
// speedup vs baseline: 1.2576x; 1.2576x over previous
#include <cuda_runtime.h>
#include <cuda_bf16.h>
#include <math.h>

// Problem constants
#define B_     64
#define S_     2048
#define D_     768
#define L_     2
#define POOL_  30
#define LEN_   5
#define TOPK_  5
#define SS_    16           // S split count
#define SCHUNK_ (S_ / SS_)  // 128

// Output layout (flattened tuple, fp32):
#define NB_ELEMS   (L_ * B_ * (TOPK_*LEN_) * D_)   // 2457600
#define OFF_SB     0
#define OFF_TB     (NB_ELEMS)
#define OFF_SSIM   (2 * NB_ELEMS)
#define OFF_TSIM   (OFF_SSIM + B_ * POOL_)
#define OFF_SRED   (OFF_TSIM + B_ * POOL_)
#define OFF_TRED   (OFF_SRED + 1)

// Device scratch
__device__ float g_partial[SS_ * B_ * D_];   // 3 MB partial sums
__device__ int   g_sidx[B_ * TOPK_];
__device__ int   g_tidx[B_ * TOPK_];
__device__ float g_stop[B_];
__device__ float g_ttop[B_];

// ---------------------------------------------------------------------------
// Kernel A: partial mean over S chunks.  grid (B, SS), block 192 (float4/d)
// Streaming loads: x is touched exactly once; keep it out of L2's working set.
// ---------------------------------------------------------------------------
__global__ void __launch_bounds__(192) k_mean_partial(const float* __restrict__ x) {
    int b  = blockIdx.x;
    int ss = blockIdx.y;
    int d4 = threadIdx.x;                     // 0..191, each owns 4 d's
    const float4* xp = reinterpret_cast<const float4*>(x)
                     + ((size_t)(b * S_ + ss * SCHUNK_)) * (D_ / 4) + d4;
    float4 acc = make_float4(0.f, 0.f, 0.f, 0.f);
#pragma unroll 8
    for (int s = 0; s < SCHUNK_; ++s) {
        float4 v = __ldcs(&xp[(size_t)s * (D_ / 4)]);
        acc.x += v.x; acc.y += v.y; acc.z += v.z; acc.w += v.w;
    }
    reinterpret_cast<float4*>(g_partial)[(ss * B_ + b) * (D_ / 4) + d4] = acc;
}

// ---------------------------------------------------------------------------
// Block reduce helper (256 threads)
// ---------------------------------------------------------------------------
__device__ __forceinline__ float block_reduce_256(float v, float* red) {
    int lane = threadIdx.x & 31, w = threadIdx.x >> 5;
#pragma unroll
    for (int o = 16; o; o >>= 1) v += __shfl_down_sync(0xffffffffu, v, o);
    if (lane == 0) red[w] = v;
    __syncthreads();
    if (w == 0) {
        v = (lane < 8) ? red[lane] : 0.f;
#pragma unroll
        for (int o = 4; o; o >>= 1) v += __shfl_down_sync(0xffffffffu, v, o);
        if (lane == 0) red[0] = v;
    }
    __syncthreads();
    return red[0];
}

// ---------------------------------------------------------------------------
// Kernel C: finalize per-batch: mean -> norm -> 60 dots (keys normalized on
// the fly: dot(k,x)*rsqrt(||k||^2)) -> top-5.   grid 64, block 256
// ---------------------------------------------------------------------------
__global__ void __launch_bounds__(256) k_finalize(const float* __restrict__ skey,
                                                  const float* __restrict__ tkey,
                                                  float* __restrict__ out) {
    int b = blockIdx.x;
    __shared__ float xn[D_];
    __shared__ float sim[2 * POOL_];
    __shared__ float red[8];

    // mean over 16 partials, accumulate |x_mean|^2
    float sq = 0.f;
    for (int d = threadIdx.x; d < D_; d += 256) {
        float s = 0.f;
#pragma unroll
        for (int ss = 0; ss < SS_; ++ss) s += g_partial[(ss * B_ + b) * D_ + d];
        float xm = s * (1.f / (float)S_);
        xn[d] = xm;
        sq += xm * xm;
    }
    float total = block_reduce_256(sq, red);
    float inv = rsqrtf(fmaxf(total, 1e-12f));
    for (int d = threadIdx.x; d < D_; d += 256) xn[d] *= inv;
    __syncthreads();

    // 60 dots: warp per key, round-robin; normalize key inline
    int lane = threadIdx.x & 31, w = threadIdx.x >> 5;   // 8 warps
    for (int key = w; key < 2 * POOL_; key += 8) {
        const float* kp = (key < POOL_) ? (skey + key * D_)
                                        : (tkey + (key - POOL_) * D_);
        float dot = 0.f, kk = 0.f;
#pragma unroll
        for (int i = 0; i < D_ / 32; ++i) {
            int d = lane + i * 32;
            float kv = __ldg(&kp[d]);
            dot += kv * xn[d];
            kk  += kv * kv;
        }
#pragma unroll
        for (int o = 16; o; o >>= 1) {
            dot += __shfl_down_sync(0xffffffffu, dot, o);
            kk  += __shfl_down_sync(0xffffffffu, kk, o);
        }
        if (lane == 0) {
            float sv = dot * rsqrtf(fmaxf(kk, 1e-12f));
            sim[key] = sv;
            if (key < POOL_) out[OFF_SSIM + b * POOL_ + key] = sv;
            else             out[OFF_TSIM + b * POOL_ + (key - POOL_)] = sv;
        }
    }
    __syncthreads();

    // top-5 selection (threads 0 and 1); strict '>' keeps lowest index on ties
    if (threadIdx.x < 2) {
        const float* sm = sim + threadIdx.x * POOL_;
        int*   gi = (threadIdx.x == 0) ? g_sidx : g_tidx;
        float* gt = (threadIdx.x == 0) ? g_stop : g_ttop;
        float loc[POOL_];
#pragma unroll
        for (int i = 0; i < POOL_; ++i) loc[i] = sm[i];
        float topsum = 0.f;
#pragma unroll
        for (int k = 0; k < TOPK_; ++k) {
            int   bj = 0;
            float bv = loc[0];
#pragma unroll
            for (int i = 1; i < POOL_; ++i) {
                if (loc[i] > bv) { bv = loc[i]; bj = i; }
            }
            gi[b * TOPK_ + k] = bj;
            topsum += bv;
            loc[bj] = -INFINITY;
        }
        gt[b] = topsum;
    }
}

// ---------------------------------------------------------------------------
// Kernel D: gather prompts + scalars.
// grid 640 = (tensor 2) x (b 64) x (k 5); block 256.
// Each block copies L_*LEN_ = 10 rows of 768 floats (1920 float4).
// Block 0 threads 0/1 also emit the reduce-sim scalars.
// ---------------------------------------------------------------------------
__global__ void __launch_bounds__(256) k_gather(const float* __restrict__ sp,
                                                const float* __restrict__ tp,
                                                float* __restrict__ out) {
    int bi = blockIdx.x;
    int tensor = bi / (B_ * TOPK_);
    int rem    = bi % (B_ * TOPK_);
    int b  = rem / TOPK_;
    int k  = rem % TOPK_;

    if (bi == 0 && threadIdx.x < 2) {
        float s = 0.f;
        const float* g = (threadIdx.x == 0) ? g_stop : g_ttop;
        for (int i = 0; i < B_; ++i) s += g[i];
        out[(threadIdx.x == 0) ? OFF_SRED : OFF_TRED] = s / (float)B_;
    }

    int idx = tensor ? g_tidx[b * TOPK_ + k] : g_sidx[b * TOPK_ + k];
    const float* srcbase = tensor ? tp : sp;
    float* outbase = out + (tensor ? OFF_TB : OFF_SB);

    // 10 rows: (l in 0..1) x (t in 0..4), 192 float4 per row
    const int ROWF4 = D_ / 4;                 // 192
    const int TOTF4 = L_ * LEN_ * ROWF4;      // 1920
#pragma unroll
    for (int i = threadIdx.x; i < TOTF4; i += 256) {
        int row = i / ROWF4;                  // 0..9
        int col = i % ROWF4;
        int l = row / LEN_;
        int t = row % LEN_;
        const float4* src = reinterpret_cast<const float4*>(
            srcbase + ((size_t)((l * POOL_ + idx) * LEN_ + t)) * D_);
        float4* dst = reinterpret_cast<float4*>(
            outbase + ((size_t)((l * B_ + b) * (TOPK_ * LEN_) + k * LEN_ + t)) * D_);
        __stcs(&dst[col], __ldg(&src[col]));
    }
}

// ---------------------------------------------------------------------------
extern "C" void kernel_launch(void* const* d_in, const int* in_sizes, int n_in,
                              void* d_out, int out_size) {
    (void)in_sizes; (void)n_in; (void)out_size;
    const float* x_embed  = (const float*)d_in[0];
    const float* s_prompt = (const float*)d_in[1];
    const float* t_prompt = (const float*)d_in[2];
    const float* s_key    = (const float*)d_in[3];
    const float* t_key    = (const float*)d_in[4];
    float* out = (float*)d_out;

    k_mean_partial<<<dim3(B_, SS_), 192>>>(x_embed);
    k_finalize<<<B_, 256>>>(s_key, t_key, out);
    k_gather<<<2 * B_ * TOPK_, 256>>>(s_prompt, t_prompt, out);
}